// round 14
// baseline (speedup 1.0000x reference)
#include <cuda_runtime.h>
#include <cuda_fp16.h>
#include <cstdint>

#define D_MODEL 256
#define ARITY 32
#define NDEPTH 15
#define VOCAB 1027
#define BATCH 8192
#define KTOT 8192
#define LN_EPS 1e-5f

// ------------------------- device scratch (no allocs allowed) -----------------
__device__ __align__(16) __half g_TPh[VOCAB * D_MODEL];           // token proj + b (fp16)
__device__ __align__(16) __half g_DPh[ARITY * NDEPTH * D_MODEL];  // depth+idx proj (fp16)
__device__ __align__(16) __half g_WTsw[(size_t)D_MODEL * KTOT];   // B pre-swizzled 32KB chunks
__device__ __align__(16) float g_part[(size_t)BATCH * D_MODEL];   // fp32 tile accumulators
__device__ int g_done;
__device__ int g_tick;
__device__ int g_flag[128];

// ---------------- convW: convert+transpose W -> pre-swizzled fp16 blocks -------
// also zeroes g_part (16KB/block) and resets counters. stream-ordered pre-mega.
__global__ __launch_bounds__(256)
void convW_kernel(const float* __restrict__ W) {
    const int t = threadIdx.x;
    if (t == 0) {
        if (blockIdx.x == 0) { g_done = 0; g_tick = 0; }
        if (blockIdx.x < 128) g_flag[blockIdx.x] = 0;
    }
    {   // zero 16KB of g_part per block (512 blocks x 16KB = 8MB)
        float4 z = make_float4(0.f, 0.f, 0.f, 0.f);
        float4* pz = (float4*)g_part + (size_t)blockIdx.x * 1024 + t;
#pragma unroll
        for (int q = 0; q < 4; q++) pz[q * 256] = z;
    }
    __shared__ float ws[16][257];
    const int kc = blockIdx.x * 16;
#pragma unroll
    for (int r = 0; r < 16; r++) {
        int kg = kc + r;
        ws[r][t] = W[(size_t)(256 + (kg >> 8) * 768 + (kg & 255)) * D_MODEL + t];
    }
    __syncthreads();
    uint32_t hi[8];
#pragma unroll
    for (int p = 0; p < 8; p++) {
        __half2 h = __floats2half2_rn(ws[2 * p][t], ws[2 * p + 1][t]);
        hi[p] = *(uint32_t*)&h;
    }
    const int c  = kc >> 6;
    const int ko = (kc & 63) >> 3;
    char* base = (char*)g_WTsw + (size_t)c * 32768 + (size_t)t * 128;
    const uint32_t x = (uint32_t)((t & 7) << 4);
    *(uint4*)(base + (((uint32_t)(ko * 16)) ^ x))       = make_uint4(hi[0], hi[1], hi[2], hi[3]);
    *(uint4*)(base + (((uint32_t)((ko + 1) * 16)) ^ x)) = make_uint4(hi[4], hi[5], hi[6], hi[7]);
}

// ================================ mega kernel ==================================
// grid = 296 (= 2 CTAs/SM capacity). blocks 0..15: dp, 16..39: tp, then ALL
// blocks work-steal GEMM units. unit u: tile mt=u>>2 (64 rows), K-quarter kq=u&3
// (32 chunks). Every unit REDs its fp32 partial into g_part; last finisher per
// tile (g_flag[mt] old==3) reads the sum and runs the gather+ReLU+LN epilogue.
#define NUM_UNITS 512
#define DP_BLOCKS 16
#define TP_BLOCKS 24
#define PREP_TOTAL (DP_BLOCKS + TP_BLOCKS)
#define SST 40960
#define BOFF 8192
#define MB0 81920
#define MB1 81928
#define TICK 81936
#define SMEM_BYTES 81952

__device__ __forceinline__ void ldsm4(uint32_t* r, uint32_t a) {
    asm volatile("ldmatrix.sync.aligned.m8n8.x4.shared.b16 {%0,%1,%2,%3}, [%4];"
                 : "=r"(r[0]), "=r"(r[1]), "=r"(r[2]), "=r"(r[3]) : "r"(a));
}
__device__ __forceinline__ void mma_fp16(float* c, const uint32_t* a, const uint32_t* b) {
    asm volatile(
        "mma.sync.aligned.m16n8k16.row.col.f32.f16.f16.f32 "
        "{%0,%1,%2,%3}, {%4,%5,%6,%7}, {%8,%9}, {%0,%1,%2,%3};"
        : "+f"(c[0]), "+f"(c[1]), "+f"(c[2]), "+f"(c[3])
        : "r"(a[0]), "r"(a[1]), "r"(a[2]), "r"(a[3]), "r"(b[0]), "r"(b[1]));
}
__device__ __forceinline__ int ld_acq(const int* p) {
    int v;
    asm volatile("ld.acquire.gpu.s32 %0, [%1];" : "=r"(v) : "l"(p));
    return v;
}
__device__ __forceinline__ void redf(float* p, float v) {
    asm volatile("red.global.add.f32 [%0], %1;" :: "l"(p), "f"(v) : "memory");
}
__device__ __forceinline__ void mbar_init(uint32_t a, uint32_t cnt) {
    asm volatile("mbarrier.init.shared.b64 [%0], %1;" :: "r"(a), "r"(cnt) : "memory");
}
__device__ __forceinline__ void bulkB(uint32_t dst, const void* src, uint32_t mbar) {
    asm volatile("mbarrier.arrive.expect_tx.shared.b64 _, [%0], %1;"
                 :: "r"(mbar), "r"(32768u) : "memory");
    asm volatile("cp.async.bulk.shared::cluster.global.mbarrier::complete_tx::bytes "
                 "[%0], [%1], %2, [%3];"
                 :: "r"(dst), "l"(src), "r"(32768u), "r"(mbar) : "memory");
}
__device__ __forceinline__ void mbar_wait(uint32_t a, uint32_t parity) {
    asm volatile(
        "{\n\t.reg .pred P;\n\t"
        "LW_%=:\n\t"
        "mbarrier.try_wait.parity.acquire.cta.shared::cta.b64 P, [%0], %1, 0x989680;\n\t"
        "@P bra LD_%=;\n\t"
        "bra LW_%=;\n\t"
        "LD_%=:\n\t}"
        :: "r"(a), "r"(parity) : "memory");
}
__device__ __forceinline__ void add_half8(float* hb, uint4 v) {
    const __half2* q = (const __half2*)&v;
#pragma unroll
    for (int p = 0; p < 4; p++) {
        float2 f = __half22float2(q[p]);
        hb[2 * p] += f.x;
        hb[2 * p + 1] += f.y;
    }
}

__device__ void gemm_unit(char* smem, uint32_t sb, int mt, int kq,
                          const float* __restrict__ ce,
                          const int* __restrict__ nid, const int* __restrict__ cdep,
                          const float* __restrict__ ln_g, const float* __restrict__ ln_b,
                          float* __restrict__ out) {
    const int t = threadIdx.x;
    const int lane = t & 31, w = t >> 5;
    const int wm = w & 1, wn = w >> 1;     // 2 x 4 warps; warp tile 32 x 64
    const int m0 = mt * 64;
    const int c0 = kq * 32;

    // A ldsm addressing
    const int arow0 = wm * 32 + (lane & 7) + ((lane >> 3) & 1) * 8;
    const uint32_t axor = (uint32_t)((arow0 & 7) << 4);
    const uint32_t khA = (uint32_t)((lane >> 4) * 16);
    // B ldsm addressing
    const int brow0 = wn * 64 + (lane & 7) + ((lane >> 4) & 1) * 8;
    const uint32_t bxor = (uint32_t)((lane & 7) << 4);
    const uint32_t khB = (uint32_t)(((lane >> 3) & 1) * 16);
    uint32_t arowb[2], browb[4];
#pragma unroll
    for (int i = 0; i < 2; i++) arowb[i] = (uint32_t)(arow0 + i * 16) * 128;
#pragma unroll
    for (int jp = 0; jp < 4; jp++) browb[jp] = (uint32_t)(brow0 + jp * 16) * 128;

    // A LDG/STS mapping
    const int prow = t >> 2, pcg = t & 3;
    const uint32_t prx = (uint32_t)((prow & 7) << 4);

    float acc[2][8][4];
#pragma unroll
    for (int i = 0; i < 2; i++)
#pragma unroll
        for (int j = 0; j < 8; j++)
#pragma unroll
            for (int q = 0; q < 4; q++) acc[i][j][q] = 0.f;

    float4 av[4];

    auto loadA = [&](int s) {
        const int c = c0 + s;
        const int a = c >> 2, kin = (c & 3) * 64;
        const float* p = ce + ((size_t)a * BATCH + m0 + prow) * D_MODEL + kin + pcg * 16;
#pragma unroll
        for (int q = 0; q < 4; q++) av[q] = *(const float4*)(p + q * 4);
    };
    auto stsA = [&](int buf) {
        const uint32_t da = sb + buf * SST;
        const uint32_t rbase = (uint32_t)prow * 128;
        uint32_t hv[8];
#pragma unroll
        for (int q = 0; q < 4; q++) {
            __half2 h01 = __floats2half2_rn(av[q].x, av[q].y);
            __half2 h23 = __floats2half2_rn(av[q].z, av[q].w);
            hv[2 * q]     = *(uint32_t*)&h01;
            hv[2 * q + 1] = *(uint32_t*)&h23;
        }
#pragma unroll
        for (int q = 0; q < 2; q++) {
            uint32_t off = rbase + (((uint32_t)(pcg * 32 + q * 16)) ^ prx);
            asm volatile("st.shared.v4.b32 [%0], {%1,%2,%3,%4};"
                         :: "r"(da + off), "r"(hv[4 * q]), "r"(hv[4 * q + 1]),
                            "r"(hv[4 * q + 2]), "r"(hv[4 * q + 3]));
        }
    };
    auto compute = [&](int buf) {
        const uint32_t SA = sb + buf * SST;
        const uint32_t SB = sb + buf * SST + BOFF;
#pragma unroll
        for (int kk = 0; kk < 4; kk++) {
            uint32_t ah[2][4], bh[4][4];
            const uint32_t ka = ((uint32_t)(kk * 32) + khA) ^ axor;
            const uint32_t kb = ((uint32_t)(kk * 32) + khB) ^ bxor;
#pragma unroll
            for (int i = 0; i < 2; i++) ldsm4(ah[i], SA + arowb[i] + ka);
#pragma unroll
            for (int jp = 0; jp < 4; jp++) ldsm4(bh[jp], SB + browb[jp] + kb);
#pragma unroll
            for (int i = 0; i < 2; i++)
#pragma unroll
                for (int j = 0; j < 8; j++)
                    mma_fp16(acc[i][j], ah[i], &bh[j >> 1][(j & 1) * 2]);
        }
    };

    // -------- prologue (mbars freshly initialized by caller) --------
    if (t == 0) {
        bulkB(sb + BOFF,       (const char*)g_WTsw + (size_t)(c0 + 0) * 32768, sb + MB0);
        bulkB(sb + SST + BOFF, (const char*)g_WTsw + (size_t)(c0 + 1) * 32768, sb + MB1);
    }
    loadA(0); stsA(0);
    loadA(1); stsA(1);
    if (t == 0) mbar_wait(sb + MB0, 0);
    __syncthreads();

    // -------- main loop: 32 chunks --------
    for (int s = 0; s < 32; s++) {
        const int buf = s & 1;
        if (s + 2 < 32) loadA(s + 2);
        compute(buf);
        if (t == 0 && s + 1 < 32)
            mbar_wait(sb + (buf ? MB0 : MB1), (uint32_t)(((s + 1) >> 1) & 1));
        __syncthreads();
        if (s + 2 < 32) {
            if (t == 0)
                bulkB(sb + buf * SST + BOFF,
                      (const char*)g_WTsw + (size_t)(c0 + s + 2) * 32768,
                      sb + (buf ? MB1 : MB0));
            stsA(buf);
        }
    }

    // -------- reduce partial into g_part (fp32 RED) --------
#pragma unroll
    for (int i = 0; i < 2; i++)
#pragma unroll
        for (int j = 0; j < 8; j++) {
            const int r = m0 + wm * 32 + i * 16 + (lane >> 2);
            const int c = wn * 64 + j * 8 + (lane & 3) * 2;
            float* p0 = g_part + (size_t)r * D_MODEL + c;
            float* p1 = g_part + (size_t)(r + 8) * D_MODEL + c;
            redf(p0, acc[i][j][0]); redf(p0 + 1, acc[i][j][1]);
            redf(p1, acc[i][j][2]); redf(p1 + 1, acc[i][j][3]);
        }
    __syncthreads();
    if (t == 0) {
        __threadfence();
        int old = atomicAdd(&g_flag[mt], 1);
        if (old == 3) {
            __threadfence();
            while (ld_acq(&g_done) < PREP_TOTAL) __nanosleep(64);
        }
        *(volatile int*)(smem + TICK + 4) = old;
    }
    __syncthreads();
    if (*(volatile int*)(smem + TICK + 4) != 3) return;

    // -------- last finisher: gather bias + ReLU + LN over 64 rows --------
    const int cb = lane * 8;
    float4 gg0 = *(const float4*)(ln_g + cb), gg1 = *(const float4*)(ln_g + cb + 4);
    float4 bb0 = *(const float4*)(ln_b + cb), bb1 = *(const float4*)(ln_b + cb + 4);
    const float gj[8] = {gg0.x, gg0.y, gg0.z, gg0.w, gg1.x, gg1.y, gg1.z, gg1.w};
    const float lj[8] = {bb0.x, bb0.y, bb0.z, bb0.w, bb1.x, bb1.y, bb1.z, bb1.w};

    int dvals[8];
#pragma unroll
    for (int q = 0; q < 8; q++)
        dvals[q] = cdep[(size_t)lane * BATCH + (m0 + w * 8 + q)];

#pragma unroll 2
    for (int q = 0; q < 8; q++) {
        const int r = m0 + w * 8 + q;
        float hb[8];
        {
            float4 p0 = *(const float4*)(g_part + (size_t)r * D_MODEL + cb);
            float4 p1 = *(const float4*)(g_part + (size_t)r * D_MODEL + cb + 4);
            hb[0] = p0.x; hb[1] = p0.y; hb[2] = p0.z; hb[3] = p0.w;
            hb[4] = p1.x; hb[5] = p1.y; hb[6] = p1.z; hb[7] = p1.w;
        }
        const int tk = nid[r];
        add_half8(hb, *(const uint4*)(g_TPh + tk * D_MODEL + cb));
#pragma unroll
        for (int a = 0; a < ARITY; a++) {
            const int d = __shfl_sync(0xFFFFFFFFu, dvals[q], a);
            add_half8(hb, *(const uint4*)(g_DPh + ((a * NDEPTH + d) << 8) + cb));
        }
        float s = 0.f, ss = 0.f;
#pragma unroll
        for (int x = 0; x < 8; x++) {
            hb[x] = fmaxf(hb[x], 0.f);
            s += hb[x];
            ss = fmaf(hb[x], hb[x], ss);
        }
#pragma unroll
        for (int o = 16; o > 0; o >>= 1) {
            s  += __shfl_xor_sync(0xFFFFFFFFu, s, o);
            ss += __shfl_xor_sync(0xFFFFFFFFu, ss, o);
        }
        const float mu = s * (1.f / 256.f);
        const float rs = rsqrtf(ss * (1.f / 256.f) - mu * mu + LN_EPS);

        float4 o0, o1;
        o0.x = (hb[0] - mu) * rs * gj[0] + lj[0];
        o0.y = (hb[1] - mu) * rs * gj[1] + lj[1];
        o0.z = (hb[2] - mu) * rs * gj[2] + lj[2];
        o0.w = (hb[3] - mu) * rs * gj[3] + lj[3];
        o1.x = (hb[4] - mu) * rs * gj[4] + lj[4];
        o1.y = (hb[5] - mu) * rs * gj[5] + lj[5];
        o1.z = (hb[6] - mu) * rs * gj[6] + lj[6];
        o1.w = (hb[7] - mu) * rs * gj[7] + lj[7];
        *(float4*)(out + (size_t)r * D_MODEL + cb)     = o0;
        *(float4*)(out + (size_t)r * D_MODEL + cb + 4) = o1;
    }
}

// ---------------- prep bodies (256 threads) -------------------------------------
__device__ void dp_body(int blk, char* sbuf,
                        const float* __restrict__ depth_emb,
                        const float* __restrict__ idx_emb,
                        const float* __restrict__ W) {
    float* de_s = (float*)sbuf;
    float* ie_s = de_s + NDEPTH * D_MODEL;
    const int j = threadIdx.x;
    for (int i = j; i < NDEPTH * D_MODEL; i += 256) de_s[i] = depth_emb[i];
    __syncthreads();
#pragma unroll
    for (int half = 0; half < 2; half++) {
        const int a = blk * 2 + half;
        ie_s[j] = idx_emb[a * D_MODEL + j];
        __syncthreads();
        float acc[NDEPTH];
#pragma unroll
        for (int m = 0; m < NDEPTH; m++) acc[m] = 0.f;
        float acci = 0.f;
        const float* Wde = W + (size_t)(512 + a * 768) * D_MODEL + j;
        const float* Wie = W + (size_t)(768 + a * 768) * D_MODEL + j;
#pragma unroll 8
        for (int k = 0; k < D_MODEL; k++) {
            float wde = Wde[k * D_MODEL];
            float wie = Wie[k * D_MODEL];
            acci = fmaf(ie_s[k], wie, acci);
#pragma unroll
            for (int m = 0; m < NDEPTH; m++)
                acc[m] = fmaf(de_s[m * D_MODEL + k], wde, acc[m]);
        }
#pragma unroll
        for (int m = 0; m < NDEPTH; m++)
            g_DPh[(a * NDEPTH + m) * D_MODEL + j] = __float2half_rn(acc[m] + acci);
        __syncthreads();
    }
    __threadfence();
    if (threadIdx.x == 0) atomicAdd(&g_done, 1);
}

__device__ void tp_body(int blk, char* sbuf,
                        const float* __restrict__ token_emb,
                        const float* __restrict__ W,
                        const float* __restrict__ bvec) {
    float* te_s = (float*)sbuf;
    const int j = threadIdx.x;
    const float bj = bvec[j];
    const float* Wt = W + j;
    for (int c = 0; c < 6; c++) {
        const int v0 = blk * 48 + c * 8;
        if (v0 >= VOCAB) break;
#pragma unroll
        for (int m = 0; m < 8; m++) {
            int v = v0 + m;
            te_s[m * D_MODEL + j] = (v < VOCAB) ? token_emb[v * D_MODEL + j] : 0.f;
        }
        __syncthreads();
        float acc[8];
#pragma unroll
        for (int m = 0; m < 8; m++) acc[m] = bj;
#pragma unroll 8
        for (int k = 0; k < D_MODEL; k++) {
            float wv = Wt[k * D_MODEL];
#pragma unroll
            for (int m = 0; m < 8; m++)
                acc[m] = fmaf(te_s[m * D_MODEL + k], wv, acc[m]);
        }
#pragma unroll
        for (int m = 0; m < 8; m++) {
            int v = v0 + m;
            if (v < VOCAB) g_TPh[v * D_MODEL + j] = __float2half_rn(acc[m]);
        }
        __syncthreads();
    }
    __threadfence();
    if (threadIdx.x == 0) atomicAdd(&g_done, 1);
}

__global__ __launch_bounds__(256, 2)
void mega_kernel(const float* __restrict__ ce,
                 const float* __restrict__ depth_emb,
                 const float* __restrict__ idx_emb,
                 const float* __restrict__ token_emb,
                 const float* __restrict__ W,
                 const float* __restrict__ bvec,
                 const int* __restrict__ nid,
                 const int* __restrict__ cdep,
                 const float* __restrict__ ln_g,
                 const float* __restrict__ ln_b,
                 float* __restrict__ out) {
    extern __shared__ char smem[];
    uint32_t sb;
    asm("{ .reg .u64 t; cvta.to.shared.u64 t, %1; cvt.u32.u64 %0, t; }"
        : "=r"(sb) : "l"(smem));
    const int b = blockIdx.x;
    if (b < DP_BLOCKS) dp_body(b, smem, depth_emb, idx_emb, W);
    else if (b < PREP_TOTAL) tp_body(b - DP_BLOCKS, smem, token_emb, W, bvec);

    // ---- work-stealing GEMM units ----
    for (;;) {
        __syncthreads();
        if (threadIdx.x == 0) {
            int u = atomicAdd(&g_tick, 1);
            *(volatile int*)(smem + TICK) = u;
            if (u < NUM_UNITS) {
                asm volatile("mbarrier.init.shared.b64 [%0], %1;"
                             :: "r"(sb + MB0), "r"(1u) : "memory");
                asm volatile("mbarrier.init.shared.b64 [%0], %1;"
                             :: "r"(sb + MB1), "r"(1u) : "memory");
            }
        }
        __syncthreads();
        const int u = *(volatile int*)(smem + TICK);
        if (u >= NUM_UNITS) return;
        gemm_unit(smem, sb, u >> 2, u & 3, ce, nid, cdep, ln_g, ln_b, out);
    }
}

// --------------------------------- launch -------------------------------------
extern "C" void kernel_launch(void* const* d_in, const int* in_sizes, int n_in,
                              void* d_out, int out_size) {
    const int*   nid          = (const int*)d_in[0];
    const float* child_embs   = (const float*)d_in[1];
    const int*   child_depths = (const int*)d_in[2];
    const float* token_emb    = (const float*)d_in[3];
    const float* depth_emb    = (const float*)d_in[4];
    const float* idx_emb      = (const float*)d_in[5];
    const float* W            = (const float*)d_in[6];
    const float* bvec         = (const float*)d_in[7];
    const float* ln_g         = (const float*)d_in[8];
    const float* ln_b         = (const float*)d_in[9];
    float* out = (float*)d_out;

    cudaFuncSetAttribute(mega_kernel, cudaFuncAttributeMaxDynamicSharedMemorySize, SMEM_BYTES);

    convW_kernel<<<KTOT / 16, 256>>>(W);
    mega_kernel<<<296, 256, SMEM_BYTES>>>(
        child_embs, depth_emb, idx_emb, token_emb, W, bvec,
        nid, child_depths, ln_g, ln_b, out);
}

// round 15
// speedup vs baseline: 1.5155x; 1.5155x over previous
#include <cuda_runtime.h>
#include <cuda_fp16.h>
#include <cstdint>

#define D_MODEL 256
#define ARITY 32
#define NDEPTH 15
#define VOCAB 1027
#define BATCH 8192
#define KTOT 8192
#define LN_EPS 1e-5f

// ------------------------- device scratch (no allocs allowed) -----------------
__device__ __align__(16) __half g_TPh[VOCAB * D_MODEL];           // token proj + b (fp16)
__device__ __align__(16) __half g_DPh[ARITY * NDEPTH * D_MODEL];  // depth+idx proj (fp16)
__device__ __align__(16) __half g_WTsw[(size_t)D_MODEL * KTOT];   // B pre-swizzled 32KB chunks
__device__ __align__(16) float g_part[(size_t)BATCH * D_MODEL];   // split-K partials
__device__ __align__(16) float g_bias[(size_t)BATCH * D_MODEL];   // per-row bias (precomputed)
__device__ int g_done;
__device__ int g_bdone;
__device__ int g_flag[256];   // per (tile, kh)

// ---------------- convW: convert+transpose W -> pre-swizzled fp16 blocks -------
__global__ __launch_bounds__(256)
void convW_kernel(const float* __restrict__ W) {
    const int t = threadIdx.x;
    if (t == 0) {
        if (blockIdx.x == 0) { g_done = 0; g_bdone = 0; }
        if (blockIdx.x < 256) g_flag[blockIdx.x] = 0;
    }
    __shared__ float ws[16][257];
    const int kc = blockIdx.x * 16;
#pragma unroll
    for (int r = 0; r < 16; r++) {
        int kg = kc + r;
        ws[r][t] = W[(size_t)(256 + (kg >> 8) * 768 + (kg & 255)) * D_MODEL + t];
    }
    __syncthreads();
    uint32_t hi[8];
#pragma unroll
    for (int p = 0; p < 8; p++) {
        __half2 h = __floats2half2_rn(ws[2 * p][t], ws[2 * p + 1][t]);
        hi[p] = *(uint32_t*)&h;
    }
    const int c  = kc >> 6;
    const int ko = (kc & 63) >> 3;
    char* base = (char*)g_WTsw + (size_t)c * 32768 + (size_t)t * 128;
    const uint32_t x = (uint32_t)((t & 7) << 4);
    *(uint4*)(base + (((uint32_t)(ko * 16)) ^ x))       = make_uint4(hi[0], hi[1], hi[2], hi[3]);
    *(uint4*)(base + (((uint32_t)((ko + 1) * 16)) ^ x)) = make_uint4(hi[4], hi[5], hi[6], hi[7]);
}

// ================================ mega kernel ==================================
// blocks [0,256): GEMM split-K (mt=b>>1, kh=b&1), R13's proven body.
// blocks [256,272): dp tables  [272,296): tp tables; then ALL 40 prep blocks
// precompute g_bias rows while the GEMM runs. grid = 296 = resident capacity.
#define GEMM_BLOCKS 256
#define DP_BLOCKS 16
#define TP_BLOCKS 24
#define PREP_TOTAL (DP_BLOCKS + TP_BLOCKS)
#define ROWS_PER_PREP 205
#define SST 40960
#define BOFF 8192
#define MB0 81920
#define MB1 81928
#define SMEM_BYTES 81952

__device__ __forceinline__ void ldsm4(uint32_t* r, uint32_t a) {
    asm volatile("ldmatrix.sync.aligned.m8n8.x4.shared.b16 {%0,%1,%2,%3}, [%4];"
                 : "=r"(r[0]), "=r"(r[1]), "=r"(r[2]), "=r"(r[3]) : "r"(a));
}
__device__ __forceinline__ void mma_fp16(float* c, const uint32_t* a, const uint32_t* b) {
    asm volatile(
        "mma.sync.aligned.m16n8k16.row.col.f32.f16.f16.f32 "
        "{%0,%1,%2,%3}, {%4,%5,%6,%7}, {%8,%9}, {%0,%1,%2,%3};"
        : "+f"(c[0]), "+f"(c[1]), "+f"(c[2]), "+f"(c[3])
        : "r"(a[0]), "r"(a[1]), "r"(a[2]), "r"(a[3]), "r"(b[0]), "r"(b[1]));
}
__device__ __forceinline__ int ld_acq(const int* p) {
    int v;
    asm volatile("ld.acquire.gpu.s32 %0, [%1];" : "=r"(v) : "l"(p));
    return v;
}
__device__ __forceinline__ void mbar_init(uint32_t a, uint32_t cnt) {
    asm volatile("mbarrier.init.shared.b64 [%0], %1;" :: "r"(a), "r"(cnt) : "memory");
}
__device__ __forceinline__ void bulkB(uint32_t dst, const void* src, uint32_t mbar) {
    asm volatile("mbarrier.arrive.expect_tx.shared.b64 _, [%0], %1;"
                 :: "r"(mbar), "r"(32768u) : "memory");
    asm volatile("cp.async.bulk.shared::cluster.global.mbarrier::complete_tx::bytes "
                 "[%0], [%1], %2, [%3];"
                 :: "r"(dst), "l"(src), "r"(32768u), "r"(mbar) : "memory");
}
__device__ __forceinline__ void mbar_wait(uint32_t a, uint32_t parity) {
    asm volatile(
        "{\n\t.reg .pred P;\n\t"
        "LW_%=:\n\t"
        "mbarrier.try_wait.parity.acquire.cta.shared::cta.b64 P, [%0], %1, 0x989680;\n\t"
        "@P bra LD_%=;\n\t"
        "bra LW_%=;\n\t"
        "LD_%=:\n\t}"
        :: "r"(a), "r"(parity) : "memory");
}
__device__ __forceinline__ void add_half8(float* hb, uint4 v) {
    const __half2* q = (const __half2*)&v;
#pragma unroll
    for (int p = 0; p < 4; p++) {
        float2 f = __half22float2(q[p]);
        hb[2 * p] += f.x;
        hb[2 * p + 1] += f.y;
    }
}

__device__ void gemm_body(char* smem, int mt, int kh, const float* __restrict__ ce,
                          const float* __restrict__ ln_g, const float* __restrict__ ln_b,
                          float* __restrict__ out) {
    uint32_t sb;
    asm("{ .reg .u64 t; cvta.to.shared.u64 t, %1; cvt.u32.u64 %0, t; }"
        : "=r"(sb) : "l"(smem));
    const int t = threadIdx.x;
    const int lane = t & 31, w = t >> 5;
    const int wm = w & 1, wn = w >> 1;     // 2 x 4 warps; warp tile 32 x 64
    const int m0 = mt * 64;
    const int c0 = kh * 64;

    // A ldsm addressing
    const int arow0 = wm * 32 + (lane & 7) + ((lane >> 3) & 1) * 8;
    const uint32_t axor = (uint32_t)((arow0 & 7) << 4);
    const uint32_t khA = (uint32_t)((lane >> 4) * 16);
    // B ldsm addressing
    const int brow0 = wn * 64 + (lane & 7) + ((lane >> 4) & 1) * 8;
    const uint32_t bxor = (uint32_t)((lane & 7) << 4);
    const uint32_t khB = (uint32_t)(((lane >> 3) & 1) * 16);
    uint32_t arowb[2], browb[4];
#pragma unroll
    for (int i = 0; i < 2; i++) arowb[i] = (uint32_t)(arow0 + i * 16) * 128;
#pragma unroll
    for (int jp = 0; jp < 4; jp++) browb[jp] = (uint32_t)(brow0 + jp * 16) * 128;

    // A LDG/STS mapping
    const int prow = t >> 2, pcg = t & 3;
    const uint32_t prx = (uint32_t)((prow & 7) << 4);

    float acc[2][8][4];
#pragma unroll
    for (int i = 0; i < 2; i++)
#pragma unroll
        for (int j = 0; j < 8; j++)
#pragma unroll
            for (int q = 0; q < 4; q++) acc[i][j][q] = 0.f;

    float4 av[4];

    auto loadA = [&](int s) {
        const int c = c0 + s;
        const int a = c >> 2, kin = (c & 3) * 64;
        const float* p = ce + ((size_t)a * BATCH + m0 + prow) * D_MODEL + kin + pcg * 16;
#pragma unroll
        for (int q = 0; q < 4; q++) av[q] = *(const float4*)(p + q * 4);
    };
    auto stsA = [&](int buf) {
        const uint32_t da = sb + buf * SST;
        const uint32_t rbase = (uint32_t)prow * 128;
        uint32_t hv[8];
#pragma unroll
        for (int q = 0; q < 4; q++) {
            __half2 h01 = __floats2half2_rn(av[q].x, av[q].y);
            __half2 h23 = __floats2half2_rn(av[q].z, av[q].w);
            hv[2 * q]     = *(uint32_t*)&h01;
            hv[2 * q + 1] = *(uint32_t*)&h23;
        }
#pragma unroll
        for (int q = 0; q < 2; q++) {
            uint32_t off = rbase + (((uint32_t)(pcg * 32 + q * 16)) ^ prx);
            asm volatile("st.shared.v4.b32 [%0], {%1,%2,%3,%4};"
                         :: "r"(da + off), "r"(hv[4 * q]), "r"(hv[4 * q + 1]),
                            "r"(hv[4 * q + 2]), "r"(hv[4 * q + 3]));
        }
    };
    auto compute = [&](int buf) {
        const uint32_t SA = sb + buf * SST;
        const uint32_t SB = sb + buf * SST + BOFF;
#pragma unroll
        for (int kk = 0; kk < 4; kk++) {
            uint32_t ah[2][4], bh[4][4];
            const uint32_t ka = ((uint32_t)(kk * 32) + khA) ^ axor;
            const uint32_t kb = ((uint32_t)(kk * 32) + khB) ^ bxor;
#pragma unroll
            for (int i = 0; i < 2; i++) ldsm4(ah[i], SA + arowb[i] + ka);
#pragma unroll
            for (int jp = 0; jp < 4; jp++) ldsm4(bh[jp], SB + browb[jp] + kb);
#pragma unroll
            for (int i = 0; i < 2; i++)
#pragma unroll
                for (int j = 0; j < 8; j++)
                    mma_fp16(acc[i][j], ah[i], &bh[j >> 1][(j & 1) * 2]);
        }
    };

    // -------- prologue --------
    if (t == 0) { mbar_init(sb + MB0, 1); mbar_init(sb + MB1, 1); }
    __syncthreads();
    if (t == 0) {
        bulkB(sb + BOFF,       (const char*)g_WTsw + (size_t)(c0 + 0) * 32768, sb + MB0);
        bulkB(sb + SST + BOFF, (const char*)g_WTsw + (size_t)(c0 + 1) * 32768, sb + MB1);
    }
    loadA(0); stsA(0);
    loadA(1); stsA(1);
    if (t == 0) mbar_wait(sb + MB0, 0);
    __syncthreads();

    // -------- main loop --------
    for (int s = 0; s < 64; s++) {
        const int buf = s & 1;
        if (s + 2 < 64) loadA(s + 2);
        compute(buf);
        if (t == 0 && s + 1 < 64)
            mbar_wait(sb + (buf ? MB0 : MB1), (uint32_t)(((s + 1) >> 1) & 1));
        __syncthreads();
        if (s + 2 < 64) {
            if (t == 0)
                bulkB(sb + buf * SST + BOFF,
                      (const char*)g_WTsw + (size_t)(c0 + s + 2) * 32768,
                      sb + (buf ? MB1 : MB0));
            stsA(buf);
        }
    }

    // ---------------- symmetric epilogue: each CTA owns 32 rows -----------------
    float* sh = (float*)smem;  // [32][260]
    if (wm == kh) {
        const int rb = lane >> 2;
        const int cbase = wn * 64 + (lane & 3) * 2;
#pragma unroll
        for (int i = 0; i < 2; i++)
#pragma unroll
            for (int j = 0; j < 8; j++) {
                const int rr = i * 16 + rb;
                const int cc = cbase + j * 8;
                sh[rr * 260 + cc]           = acc[i][j][0];
                sh[rr * 260 + cc + 1]       = acc[i][j][1];
                sh[(rr + 8) * 260 + cc]     = acc[i][j][2];
                sh[(rr + 8) * 260 + cc + 1] = acc[i][j][3];
            }
    } else {
#pragma unroll
        for (int i = 0; i < 2; i++)
#pragma unroll
            for (int j = 0; j < 8; j++) {
                const int r = m0 + wm * 32 + i * 16 + (lane >> 2);
                const int c = wn * 64 + j * 8 + (lane & 3) * 2;
                *(float2*)(g_part + (size_t)r * D_MODEL + c) =
                    make_float2(acc[i][j][0], acc[i][j][1]);
                *(float2*)(g_part + (size_t)(r + 8) * D_MODEL + c) =
                    make_float2(acc[i][j][2], acc[i][j][3]);
            }
    }
    __syncthreads();
    __threadfence();
    if (t == 0) {
        atomicAdd(&g_flag[2 * mt + kh], 1);
        while (ld_acq(&g_bdone) < PREP_TOTAL) __nanosleep(64);             // bias ready
        while (ld_acq(&g_flag[2 * mt + (1 - kh)]) == 0) __nanosleep(64);   // partner
    }
    __syncthreads();

    // epilogue over 32 owned rows: warp w handles 4 rows
    const int cb = lane * 8;
    float4 gg0 = *(const float4*)(ln_g + cb), gg1 = *(const float4*)(ln_g + cb + 4);
    float4 bb0 = *(const float4*)(ln_b + cb), bb1 = *(const float4*)(ln_b + cb + 4);
    const float gj[8] = {gg0.x, gg0.y, gg0.z, gg0.w, gg1.x, gg1.y, gg1.z, gg1.w};
    const float lj[8] = {bb0.x, bb0.y, bb0.z, bb0.w, bb1.x, bb1.y, bb1.z, bb1.w};
    const int rbase = m0 + kh * 32 + w * 4;

#pragma unroll
    for (int q = 0; q < 4; q++) {
        const int r = rbase + q;
        float hb[8];
        const float* sp = sh + (w * 4 + q) * 260 + cb;
#pragma unroll
        for (int x = 0; x < 8; x++) hb[x] = sp[x];

        {   // partner's K-half partial
            float4 p0 = *(const float4*)(g_part + (size_t)r * D_MODEL + cb);
            float4 p1 = *(const float4*)(g_part + (size_t)r * D_MODEL + cb + 4);
            hb[0] += p0.x; hb[1] += p0.y; hb[2] += p0.z; hb[3] += p0.w;
            hb[4] += p1.x; hb[5] += p1.y; hb[6] += p1.z; hb[7] += p1.w;
        }
        {   // precomputed bias row
            float4 b0 = *(const float4*)(g_bias + (size_t)r * D_MODEL + cb);
            float4 b1 = *(const float4*)(g_bias + (size_t)r * D_MODEL + cb + 4);
            hb[0] += b0.x; hb[1] += b0.y; hb[2] += b0.z; hb[3] += b0.w;
            hb[4] += b1.x; hb[5] += b1.y; hb[6] += b1.z; hb[7] += b1.w;
        }

        float s = 0.f, ss = 0.f;
#pragma unroll
        for (int x = 0; x < 8; x++) {
            hb[x] = fmaxf(hb[x], 0.f);
            s += hb[x];
            ss = fmaf(hb[x], hb[x], ss);
        }
#pragma unroll
        for (int o = 16; o > 0; o >>= 1) {
            s  += __shfl_xor_sync(0xFFFFFFFFu, s, o);
            ss += __shfl_xor_sync(0xFFFFFFFFu, ss, o);
        }
        const float mu = s * (1.f / 256.f);
        const float rs = rsqrtf(ss * (1.f / 256.f) - mu * mu + LN_EPS);

        float4 o0, o1;
        o0.x = (hb[0] - mu) * rs * gj[0] + lj[0];
        o0.y = (hb[1] - mu) * rs * gj[1] + lj[1];
        o0.z = (hb[2] - mu) * rs * gj[2] + lj[2];
        o0.w = (hb[3] - mu) * rs * gj[3] + lj[3];
        o1.x = (hb[4] - mu) * rs * gj[4] + lj[4];
        o1.y = (hb[5] - mu) * rs * gj[5] + lj[5];
        o1.z = (hb[6] - mu) * rs * gj[6] + lj[6];
        o1.w = (hb[7] - mu) * rs * gj[7] + lj[7];
        *(float4*)(out + (size_t)r * D_MODEL + cb)     = o0;
        *(float4*)(out + (size_t)r * D_MODEL + cb + 4) = o1;
    }
}

// ---------------- prep bodies (256 threads) ------------------------------------
__device__ void dp_body(int blk, char* sbuf,
                        const float* __restrict__ depth_emb,
                        const float* __restrict__ idx_emb,
                        const float* __restrict__ W) {
    float* de_s = (float*)sbuf;
    float* ie_s = de_s + NDEPTH * D_MODEL;
    const int j = threadIdx.x;
    for (int i = j; i < NDEPTH * D_MODEL; i += 256) de_s[i] = depth_emb[i];
    __syncthreads();
#pragma unroll
    for (int half = 0; half < 2; half++) {
        const int a = blk * 2 + half;
        ie_s[j] = idx_emb[a * D_MODEL + j];
        __syncthreads();
        float acc[NDEPTH];
#pragma unroll
        for (int m = 0; m < NDEPTH; m++) acc[m] = 0.f;
        float acci = 0.f;
        const float* Wde = W + (size_t)(512 + a * 768) * D_MODEL + j;
        const float* Wie = W + (size_t)(768 + a * 768) * D_MODEL + j;
#pragma unroll 8
        for (int k = 0; k < D_MODEL; k++) {
            float wde = Wde[k * D_MODEL];
            float wie = Wie[k * D_MODEL];
            acci = fmaf(ie_s[k], wie, acci);
#pragma unroll
            for (int m = 0; m < NDEPTH; m++)
                acc[m] = fmaf(de_s[m * D_MODEL + k], wde, acc[m]);
        }
#pragma unroll
        for (int m = 0; m < NDEPTH; m++)
            g_DPh[(a * NDEPTH + m) * D_MODEL + j] = __float2half_rn(acc[m] + acci);
        __syncthreads();
    }
    __threadfence();
    if (threadIdx.x == 0) atomicAdd(&g_done, 1);
}

__device__ void tp_body(int blk, char* sbuf,
                        const float* __restrict__ token_emb,
                        const float* __restrict__ W,
                        const float* __restrict__ bvec) {
    float* te_s = (float*)sbuf;
    const int j = threadIdx.x;
    const float bj = bvec[j];
    const float* Wt = W + j;
    for (int c = 0; c < 6; c++) {
        const int v0 = blk * 48 + c * 8;
        if (v0 >= VOCAB) break;
#pragma unroll
        for (int m = 0; m < 8; m++) {
            int v = v0 + m;
            te_s[m * D_MODEL + j] = (v < VOCAB) ? token_emb[v * D_MODEL + j] : 0.f;
        }
        __syncthreads();
        float acc[8];
#pragma unroll
        for (int m = 0; m < 8; m++) acc[m] = bj;
#pragma unroll 8
        for (int k = 0; k < D_MODEL; k++) {
            float wv = Wt[k * D_MODEL];
#pragma unroll
            for (int m = 0; m < 8; m++)
                acc[m] = fmaf(te_s[m * D_MODEL + k], wv, acc[m]);
        }
#pragma unroll
        for (int m = 0; m < 8; m++) {
            int v = v0 + m;
            if (v < VOCAB) g_TPh[v * D_MODEL + j] = __float2half_rn(acc[m]);
        }
        __syncthreads();
    }
    __threadfence();
    if (threadIdx.x == 0) atomicAdd(&g_done, 1);
}

// bias pass: 40 prep CTAs compute g_bias rows while GEMM runs
__device__ void bias_body(int pb, const int* __restrict__ nid,
                          const int* __restrict__ cdep) {
    // wait for all tables
    if (threadIdx.x == 0) {
        while (ld_acq(&g_done) < PREP_TOTAL) __nanosleep(128);
    }
    __syncthreads();

    const int lane = threadIdx.x & 31, w = threadIdx.x >> 5;
    const int cb = lane * 8;
    const int r0 = pb * ROWS_PER_PREP;
    const int r1 = min(r0 + ROWS_PER_PREP, BATCH);

    for (int r = r0 + w; r < r1; r += 8) {
        const int dv = cdep[(size_t)lane * BATCH + r];
        const int tk = nid[r];
        float hb[8];
        {
            uint4 v = *(const uint4*)(g_TPh + tk * D_MODEL + cb);
            const __half2* qh = (const __half2*)&v;
#pragma unroll
            for (int p = 0; p < 4; p++) {
                float2 f = __half22float2(qh[p]);
                hb[2 * p] = f.x;
                hb[2 * p + 1] = f.y;
            }
        }
#pragma unroll
        for (int a = 0; a < ARITY; a++) {
            const int d = __shfl_sync(0xFFFFFFFFu, dv, a);
            add_half8(hb, *(const uint4*)(g_DPh + ((a * NDEPTH + d) << 8) + cb));
        }
        *(float4*)(g_bias + (size_t)r * D_MODEL + cb) =
            make_float4(hb[0], hb[1], hb[2], hb[3]);
        *(float4*)(g_bias + (size_t)r * D_MODEL + cb + 4) =
            make_float4(hb[4], hb[5], hb[6], hb[7]);
    }
    __syncthreads();
    __threadfence();
    if (threadIdx.x == 0) atomicAdd(&g_bdone, 1);
}

__global__ __launch_bounds__(256, 2)
void mega_kernel(const float* __restrict__ ce,
                 const float* __restrict__ depth_emb,
                 const float* __restrict__ idx_emb,
                 const float* __restrict__ token_emb,
                 const float* __restrict__ W,
                 const float* __restrict__ bvec,
                 const int* __restrict__ nid,
                 const int* __restrict__ cdep,
                 const float* __restrict__ ln_g,
                 const float* __restrict__ ln_b,
                 float* __restrict__ out) {
    extern __shared__ char smem[];
    const int b = blockIdx.x;
    if (b < GEMM_BLOCKS) {
        gemm_body(smem, b >> 1, b & 1, ce, ln_g, ln_b, out);
    } else {
        const int pb = b - GEMM_BLOCKS;  // 0..39
        if (pb < DP_BLOCKS) dp_body(pb, smem, depth_emb, idx_emb, W);
        else                tp_body(pb - DP_BLOCKS, smem, token_emb, W, bvec);
        bias_body(pb, nid, cdep);
    }
}

// --------------------------------- launch -------------------------------------
extern "C" void kernel_launch(void* const* d_in, const int* in_sizes, int n_in,
                              void* d_out, int out_size) {
    const int*   nid          = (const int*)d_in[0];
    const float* child_embs   = (const float*)d_in[1];
    const int*   child_depths = (const int*)d_in[2];
    const float* token_emb    = (const float*)d_in[3];
    const float* depth_emb    = (const float*)d_in[4];
    const float* idx_emb      = (const float*)d_in[5];
    const float* W            = (const float*)d_in[6];
    const float* bvec         = (const float*)d_in[7];
    const float* ln_g         = (const float*)d_in[8];
    const float* ln_b         = (const float*)d_in[9];
    float* out = (float*)d_out;

    cudaFuncSetAttribute(mega_kernel, cudaFuncAttributeMaxDynamicSharedMemorySize, SMEM_BYTES);

    convW_kernel<<<KTOT / 16, 256>>>(W);
    mega_kernel<<<GEMM_BLOCKS + PREP_TOTAL, 256, SMEM_BYTES>>>(
        child_embs, depth_emb, idx_emb, token_emb, W, bvec,
        nid, child_depths, ln_g, ln_b, out);
}

// round 16
// speedup vs baseline: 1.8407x; 1.2145x over previous
#include <cuda_runtime.h>
#include <cuda_fp16.h>
#include <cstdint>

#define D_MODEL 256
#define ARITY 32
#define NDEPTH 15
#define VOCAB 1027
#define BATCH 8192
#define KTOT 8192
#define LN_EPS 1e-5f

// ------------------------- device scratch (no allocs allowed) -----------------
__device__ __align__(16) __half g_TPh[VOCAB * D_MODEL];           // token proj + b (fp16)
__device__ __align__(16) __half g_DPh[ARITY * NDEPTH * D_MODEL];  // depth+idx proj (fp16)
__device__ __align__(16) __half g_WTsw[(size_t)D_MODEL * KTOT];   // B pre-swizzled 32KB chunks
__device__ __align__(16) float g_part[(size_t)BATCH * D_MODEL];   // split-K partials
__device__ int g_done;
__device__ int g_flag[256];   // per (tile, kh)

// ---------------- convW: convert+transpose W -> pre-swizzled fp16 blocks -------
__global__ __launch_bounds__(256)
void convW_kernel(const float* __restrict__ W) {
    if (threadIdx.x == 0) {
        if (blockIdx.x == 0) g_done = 0;
        if (blockIdx.x < 256) g_flag[blockIdx.x] = 0;
    }
    __shared__ float ws[16][257];
    const int kc = blockIdx.x * 16;
    const int t = threadIdx.x;        // output row n
#pragma unroll
    for (int r = 0; r < 16; r++) {
        int kg = kc + r;
        ws[r][t] = W[(size_t)(256 + (kg >> 8) * 768 + (kg & 255)) * D_MODEL + t];
    }
    __syncthreads();
    uint32_t hi[8];
#pragma unroll
    for (int p = 0; p < 8; p++) {
        __half2 h = __floats2half2_rn(ws[2 * p][t], ws[2 * p + 1][t]);
        hi[p] = *(uint32_t*)&h;
    }
    const int c  = kc >> 6;
    const int ko = (kc & 63) >> 3;
    char* base = (char*)g_WTsw + (size_t)c * 32768 + (size_t)t * 128;
    const uint32_t x = (uint32_t)((t & 7) << 4);
    *(uint4*)(base + (((uint32_t)(ko * 16)) ^ x))       = make_uint4(hi[0], hi[1], hi[2], hi[3]);
    *(uint4*)(base + (((uint32_t)((ko + 1) * 16)) ^ x)) = make_uint4(hi[4], hi[5], hi[6], hi[7]);
}

// ================================ mega kernel ==================================
#define GEMM_BLOCKS 256
#define DP_BLOCKS 16
#define TP_BLOCKS 24
#define PREP_TOTAL (DP_BLOCKS + TP_BLOCKS)
#define SST 40960
#define BOFF 8192
#define MB0 81920
#define MB1 81928
#define SMEM_BYTES 81952

__device__ __forceinline__ void ldsm4(uint32_t* r, uint32_t a) {
    asm volatile("ldmatrix.sync.aligned.m8n8.x4.shared.b16 {%0,%1,%2,%3}, [%4];"
                 : "=r"(r[0]), "=r"(r[1]), "=r"(r[2]), "=r"(r[3]) : "r"(a));
}
__device__ __forceinline__ void mma_fp16(float* c, const uint32_t* a, const uint32_t* b) {
    asm volatile(
        "mma.sync.aligned.m16n8k16.row.col.f32.f16.f16.f32 "
        "{%0,%1,%2,%3}, {%4,%5,%6,%7}, {%8,%9}, {%0,%1,%2,%3};"
        : "+f"(c[0]), "+f"(c[1]), "+f"(c[2]), "+f"(c[3])
        : "r"(a[0]), "r"(a[1]), "r"(a[2]), "r"(a[3]), "r"(b[0]), "r"(b[1]));
}
__device__ __forceinline__ int ld_acq(const int* p) {
    int v;
    asm volatile("ld.acquire.gpu.s32 %0, [%1];" : "=r"(v) : "l"(p));
    return v;
}
__device__ __forceinline__ void mbar_init(uint32_t a, uint32_t cnt) {
    asm volatile("mbarrier.init.shared.b64 [%0], %1;" :: "r"(a), "r"(cnt) : "memory");
}
__device__ __forceinline__ void bulkB(uint32_t dst, const void* src, uint32_t mbar) {
    asm volatile("mbarrier.arrive.expect_tx.shared.b64 _, [%0], %1;"
                 :: "r"(mbar), "r"(32768u) : "memory");
    asm volatile("cp.async.bulk.shared::cluster.global.mbarrier::complete_tx::bytes "
                 "[%0], [%1], %2, [%3];"
                 :: "r"(dst), "l"(src), "r"(32768u), "r"(mbar) : "memory");
}
__device__ __forceinline__ void mbar_wait(uint32_t a, uint32_t parity) {
    asm volatile(
        "{\n\t.reg .pred P;\n\t"
        "LW_%=:\n\t"
        "mbarrier.try_wait.parity.acquire.cta.shared::cta.b64 P, [%0], %1, 0x989680;\n\t"
        "@P bra LD_%=;\n\t"
        "bra LW_%=;\n\t"
        "LD_%=:\n\t}"
        :: "r"(a), "r"(parity) : "memory");
}
__device__ __forceinline__ void add_half8(float* hb, uint4 v) {
    const __half2* q = (const __half2*)&v;
#pragma unroll
    for (int p = 0; p < 4; p++) {
        float2 f = __half22float2(q[p]);
        hb[2 * p] += f.x;
        hb[2 * p + 1] += f.y;
    }
}

__device__ void gemm_body(char* smem, int mt, int kh, const float* __restrict__ ce,
                          const int* __restrict__ nid, const int* __restrict__ cdep,
                          const float* __restrict__ ln_g, const float* __restrict__ ln_b,
                          float* __restrict__ out) {
    uint32_t sb;
    asm("{ .reg .u64 t; cvta.to.shared.u64 t, %1; cvt.u32.u64 %0, t; }"
        : "=r"(sb) : "l"(smem));
    const int t = threadIdx.x;
    const int lane = t & 31, w = t >> 5;
    const int wm = w & 1, wn = w >> 1;     // 2 x 4 warps; warp tile 32 x 64
    const int m0 = mt * 64;
    const int c0 = kh * 64;

    // A ldsm addressing
    const int arow0 = wm * 32 + (lane & 7) + ((lane >> 3) & 1) * 8;
    const uint32_t axor = (uint32_t)((arow0 & 7) << 4);
    const uint32_t khA = (uint32_t)((lane >> 4) * 16);
    // B ldsm addressing
    const int brow0 = wn * 64 + (lane & 7) + ((lane >> 4) & 1) * 8;
    const uint32_t bxor = (uint32_t)((lane & 7) << 4);
    const uint32_t khB = (uint32_t)(((lane >> 3) & 1) * 16);
    uint32_t arowb[2], browb[4];
#pragma unroll
    for (int i = 0; i < 2; i++) arowb[i] = (uint32_t)(arow0 + i * 16) * 128;
#pragma unroll
    for (int jp = 0; jp < 4; jp++) browb[jp] = (uint32_t)(brow0 + jp * 16) * 128;

    // A LDG/STS mapping
    const int prow = t >> 2, pcg = t & 3;
    const uint32_t prx = (uint32_t)((prow & 7) << 4);

    float acc[2][8][4];
#pragma unroll
    for (int i = 0; i < 2; i++)
#pragma unroll
        for (int j = 0; j < 8; j++)
#pragma unroll
            for (int q = 0; q < 4; q++) acc[i][j][q] = 0.f;

    float4 av[4];

    auto loadA = [&](int s) {
        const int c = c0 + s;
        const int a = c >> 2, kin = (c & 3) * 64;
        const float* p = ce + ((size_t)a * BATCH + m0 + prow) * D_MODEL + kin + pcg * 16;
#pragma unroll
        for (int q = 0; q < 4; q++) av[q] = *(const float4*)(p + q * 4);
    };
    auto stsA = [&](int buf) {
        const uint32_t da = sb + buf * SST;
        const uint32_t rbase = (uint32_t)prow * 128;
        uint32_t hv[8];
#pragma unroll
        for (int q = 0; q < 4; q++) {
            __half2 h01 = __floats2half2_rn(av[q].x, av[q].y);
            __half2 h23 = __floats2half2_rn(av[q].z, av[q].w);
            hv[2 * q]     = *(uint32_t*)&h01;
            hv[2 * q + 1] = *(uint32_t*)&h23;
        }
#pragma unroll
        for (int q = 0; q < 2; q++) {
            uint32_t off = rbase + (((uint32_t)(pcg * 32 + q * 16)) ^ prx);
            asm volatile("st.shared.v4.b32 [%0], {%1,%2,%3,%4};"
                         :: "r"(da + off), "r"(hv[4 * q]), "r"(hv[4 * q + 1]),
                            "r"(hv[4 * q + 2]), "r"(hv[4 * q + 3]));
        }
    };
    auto compute = [&](int buf) {
        const uint32_t SA = sb + buf * SST;
        const uint32_t SB = sb + buf * SST + BOFF;
#pragma unroll
        for (int kk = 0; kk < 4; kk++) {
            uint32_t ah[2][4], bh[4][4];
            const uint32_t ka = ((uint32_t)(kk * 32) + khA) ^ axor;
            const uint32_t kb = ((uint32_t)(kk * 32) + khB) ^ bxor;
#pragma unroll
            for (int i = 0; i < 2; i++) ldsm4(ah[i], SA + arowb[i] + ka);
#pragma unroll
            for (int jp = 0; jp < 4; jp++) ldsm4(bh[jp], SB + browb[jp] + kb);
#pragma unroll
            for (int i = 0; i < 2; i++)
#pragma unroll
                for (int j = 0; j < 8; j++)
                    mma_fp16(acc[i][j], ah[i], &bh[j >> 1][(j & 1) * 2]);
        }
    };

    // -------- prologue --------
    if (t == 0) { mbar_init(sb + MB0, 1); mbar_init(sb + MB1, 1); }
    __syncthreads();
    if (t == 0) {
        bulkB(sb + BOFF,       (const char*)g_WTsw + (size_t)(c0 + 0) * 32768, sb + MB0);
        bulkB(sb + SST + BOFF, (const char*)g_WTsw + (size_t)(c0 + 1) * 32768, sb + MB1);
    }
    loadA(0); stsA(0);
    loadA(1); stsA(1);
    if (t == 0) mbar_wait(sb + MB0, 0);   // B(0) ready (leader-only)
    __syncthreads();

    // -------- main loop: compute s; leader waits B(s+1) before stage barrier ----
    for (int s = 0; s < 64; s++) {
        const int buf = s & 1;
        if (s + 2 < 64) loadA(s + 2);
        compute(buf);
        if (t == 0 && s + 1 < 64)
            mbar_wait(sb + (buf ? MB0 : MB1), (uint32_t)(((s + 1) >> 1) & 1));
        __syncthreads();  // buf fully read by all; B(s+1) visible to all
        if (s + 2 < 64) {
            if (t == 0)
                bulkB(sb + buf * SST + BOFF,
                      (const char*)g_WTsw + (size_t)(c0 + s + 2) * 32768,
                      sb + (buf ? MB1 : MB0));
            stsA(buf);  // A(s+2); readers separated by next stage's barrier
        }
    }

    // ---------------- symmetric epilogue: each CTA owns 32 rows -----------------
    // hoist epilogue global loads: latency hides under staging + flag spin
    const int cb = lane * 8;
    const int rbase = m0 + kh * 32 + w * 4;
    float4 gg0 = *(const float4*)(ln_g + cb), gg1 = *(const float4*)(ln_g + cb + 4);
    float4 bb0 = *(const float4*)(ln_b + cb), bb1 = *(const float4*)(ln_b + cb + 4);
    int dvals[4], tks[4];
#pragma unroll
    for (int q = 0; q < 4; q++) {
        dvals[q] = cdep[(size_t)lane * BATCH + (rbase + q)];
        tks[q]   = nid[rbase + q];
    }

    float* sh = (float*)smem;  // [32][260]
    if (wm == kh) {
        const int rb = lane >> 2;                 // local row within half
        const int cbase = wn * 64 + (lane & 3) * 2;
#pragma unroll
        for (int i = 0; i < 2; i++)
#pragma unroll
            for (int j = 0; j < 8; j++) {
                const int rr = i * 16 + rb;
                const int cc = cbase + j * 8;
                sh[rr * 260 + cc]           = acc[i][j][0];
                sh[rr * 260 + cc + 1]       = acc[i][j][1];
                sh[(rr + 8) * 260 + cc]     = acc[i][j][2];
                sh[(rr + 8) * 260 + cc + 1] = acc[i][j][3];
            }
    } else {
#pragma unroll
        for (int i = 0; i < 2; i++)
#pragma unroll
            for (int j = 0; j < 8; j++) {
                const int r = m0 + wm * 32 + i * 16 + (lane >> 2);
                const int c = wn * 64 + j * 8 + (lane & 3) * 2;
                *(float2*)(g_part + (size_t)r * D_MODEL + c) =
                    make_float2(acc[i][j][0], acc[i][j][1]);
                *(float2*)(g_part + (size_t)(r + 8) * D_MODEL + c) =
                    make_float2(acc[i][j][2], acc[i][j][3]);
            }
    }
    __syncthreads();
    __threadfence();
    if (t == 0) {
        atomicAdd(&g_flag[2 * mt + kh], 1);                       // my partial ready
        while (ld_acq(&g_done) < PREP_TOTAL) __nanosleep(64);      // tables ready
        while (ld_acq(&g_flag[2 * mt + (1 - kh)]) == 0) __nanosleep(64);  // partner partial
    }
    __syncthreads();

    // epilogue over 32 owned rows: warp w handles 4 rows
    const float gj[8] = {gg0.x, gg0.y, gg0.z, gg0.w, gg1.x, gg1.y, gg1.z, gg1.w};
    const float lj[8] = {bb0.x, bb0.y, bb0.z, bb0.w, bb1.x, bb1.y, bb1.z, bb1.w};

#pragma unroll
    for (int q = 0; q < 4; q++) {
        const int r = rbase + q;
        float hb[8];
        const float* sp = sh + (w * 4 + q) * 260 + cb;
#pragma unroll
        for (int x = 0; x < 8; x++) hb[x] = sp[x];

        {   // partner's K-half partial
            float4 p0 = *(const float4*)(g_part + (size_t)r * D_MODEL + cb);
            float4 p1 = *(const float4*)(g_part + (size_t)r * D_MODEL + cb + 4);
            hb[0] += p0.x; hb[1] += p0.y; hb[2] += p0.z; hb[3] += p0.w;
            hb[4] += p1.x; hb[5] += p1.y; hb[6] += p1.z; hb[7] += p1.w;
        }

        add_half8(hb, *(const uint4*)(g_TPh + tks[q] * D_MODEL + cb));
#pragma unroll
        for (int a = 0; a < ARITY; a++) {
            const int d = __shfl_sync(0xFFFFFFFFu, dvals[q], a);
            add_half8(hb, *(const uint4*)(g_DPh + ((a * NDEPTH + d) << 8) + cb));
        }

        float s = 0.f, ss = 0.f;
#pragma unroll
        for (int x = 0; x < 8; x++) {
            hb[x] = fmaxf(hb[x], 0.f);
            s += hb[x];
            ss = fmaf(hb[x], hb[x], ss);
        }
#pragma unroll
        for (int o = 16; o > 0; o >>= 1) {
            s  += __shfl_xor_sync(0xFFFFFFFFu, s, o);
            ss += __shfl_xor_sync(0xFFFFFFFFu, ss, o);
        }
        const float mu = s * (1.f / 256.f);
        const float rs = rsqrtf(ss * (1.f / 256.f) - mu * mu + LN_EPS);

        float4 o0, o1;
        o0.x = (hb[0] - mu) * rs * gj[0] + lj[0];
        o0.y = (hb[1] - mu) * rs * gj[1] + lj[1];
        o0.z = (hb[2] - mu) * rs * gj[2] + lj[2];
        o0.w = (hb[3] - mu) * rs * gj[3] + lj[3];
        o1.x = (hb[4] - mu) * rs * gj[4] + lj[4];
        o1.y = (hb[5] - mu) * rs * gj[5] + lj[5];
        o1.z = (hb[6] - mu) * rs * gj[6] + lj[6];
        o1.w = (hb[7] - mu) * rs * gj[7] + lj[7];
        *(float4*)(out + (size_t)r * D_MODEL + cb)     = o0;
        *(float4*)(out + (size_t)r * D_MODEL + cb + 4) = o1;
    }
}

// ---------------- prep bodies (256 threads; packed into 40 blocks) -------------
__device__ void dp_body(int blk, char* sbuf,
                        const float* __restrict__ depth_emb,
                        const float* __restrict__ idx_emb,
                        const float* __restrict__ W) {
    float* de_s = (float*)sbuf;
    float* ie_s = de_s + NDEPTH * D_MODEL;
    const int j = threadIdx.x;
    for (int i = j; i < NDEPTH * D_MODEL; i += 256) de_s[i] = depth_emb[i];
    __syncthreads();

#pragma unroll
    for (int half = 0; half < 2; half++) {
        const int a = blk * 2 + half;
        ie_s[j] = idx_emb[a * D_MODEL + j];
        __syncthreads();
        float acc[NDEPTH];
#pragma unroll
        for (int m = 0; m < NDEPTH; m++) acc[m] = 0.f;
        float acci = 0.f;
        const float* Wde = W + (size_t)(512 + a * 768) * D_MODEL + j;
        const float* Wie = W + (size_t)(768 + a * 768) * D_MODEL + j;
#pragma unroll 8
        for (int k = 0; k < D_MODEL; k++) {
            float wde = Wde[k * D_MODEL];
            float wie = Wie[k * D_MODEL];
            acci = fmaf(ie_s[k], wie, acci);
#pragma unroll
            for (int m = 0; m < NDEPTH; m++)
                acc[m] = fmaf(de_s[m * D_MODEL + k], wde, acc[m]);
        }
#pragma unroll
        for (int m = 0; m < NDEPTH; m++)
            g_DPh[(a * NDEPTH + m) * D_MODEL + j] = __float2half_rn(acc[m] + acci);
        __syncthreads();
    }
    __threadfence();
    if (threadIdx.x == 0) atomicAdd(&g_done, 1);
}

__device__ void tp_body(int blk, char* sbuf,
                        const float* __restrict__ token_emb,
                        const float* __restrict__ W,
                        const float* __restrict__ bvec) {
    float* te_s = (float*)sbuf;
    const int j = threadIdx.x;
    const float bj = bvec[j];
    const float* Wt = W + j;

    for (int c = 0; c < 6; c++) {
        const int v0 = blk * 48 + c * 8;
        if (v0 >= VOCAB) break;
#pragma unroll
        for (int m = 0; m < 8; m++) {
            int v = v0 + m;
            te_s[m * D_MODEL + j] = (v < VOCAB) ? token_emb[v * D_MODEL + j] : 0.f;
        }
        __syncthreads();
        float acc[8];
#pragma unroll
        for (int m = 0; m < 8; m++) acc[m] = bj;
#pragma unroll 8
        for (int k = 0; k < D_MODEL; k++) {
            float wv = Wt[k * D_MODEL];
#pragma unroll
            for (int m = 0; m < 8; m++)
                acc[m] = fmaf(te_s[m * D_MODEL + k], wv, acc[m]);
        }
#pragma unroll
        for (int m = 0; m < 8; m++) {
            int v = v0 + m;
            if (v < VOCAB) g_TPh[v * D_MODEL + j] = __float2half_rn(acc[m]);
        }
        __syncthreads();
    }
    __threadfence();
    if (threadIdx.x == 0) atomicAdd(&g_done, 1);
}

__global__ __launch_bounds__(256, 2)
void mega_kernel(const float* __restrict__ ce,
                 const float* __restrict__ depth_emb,
                 const float* __restrict__ idx_emb,
                 const float* __restrict__ token_emb,
                 const float* __restrict__ W,
                 const float* __restrict__ bvec,
                 const int* __restrict__ nid,
                 const int* __restrict__ cdep,
                 const float* __restrict__ ln_g,
                 const float* __restrict__ ln_b,
                 float* __restrict__ out) {
    extern __shared__ char smem[];
    const int b = blockIdx.x;
    if (b < GEMM_BLOCKS) gemm_body(smem, b >> 1, b & 1, ce, nid, cdep, ln_g, ln_b, out);
    else if (b < GEMM_BLOCKS + DP_BLOCKS) dp_body(b - GEMM_BLOCKS, smem, depth_emb, idx_emb, W);
    else tp_body(b - GEMM_BLOCKS - DP_BLOCKS, smem, token_emb, W, bvec);
}

// --------------------------------- launch -------------------------------------
extern "C" void kernel_launch(void* const* d_in, const int* in_sizes, int n_in,
                              void* d_out, int out_size) {
    const int*   nid          = (const int*)d_in[0];
    const float* child_embs   = (const float*)d_in[1];
    const int*   child_depths = (const int*)d_in[2];
    const float* token_emb    = (const float*)d_in[3];
    const float* depth_emb    = (const float*)d_in[4];
    const float* idx_emb      = (const float*)d_in[5];
    const float* W            = (const float*)d_in[6];
    const float* bvec         = (const float*)d_in[7];
    const float* ln_g         = (const float*)d_in[8];
    const float* ln_b         = (const float*)d_in[9];
    float* out = (float*)d_out;

    cudaFuncSetAttribute(mega_kernel, cudaFuncAttributeMaxDynamicSharedMemorySize, SMEM_BYTES);

    convW_kernel<<<KTOT / 16, 256>>>(W);
    mega_kernel<<<GEMM_BLOCKS + PREP_TOTAL, 256, SMEM_BYTES>>>(
        child_embs, depth_emb, idx_emb, token_emb, W, bvec,
        nid, child_depths, ln_g, ln_b, out);
}

// round 17
// speedup vs baseline: 1.9013x; 1.0329x over previous
#include <cuda_runtime.h>
#include <cuda_fp16.h>
#include <cstdint>

#define D_MODEL 256
#define ARITY 32
#define NDEPTH 15
#define VOCAB 1027
#define BATCH 8192
#define KTOT 8192
#define LN_EPS 1e-5f

// ------------------------- device scratch (no allocs allowed) -----------------
__device__ __align__(16) __half g_TPh[VOCAB * D_MODEL];           // token proj + b (fp16)
__device__ __align__(16) __half g_DPh[ARITY * NDEPTH * D_MODEL];  // depth+idx proj (fp16)
__device__ __align__(16) __half g_WTsw[(size_t)D_MODEL * KTOT];   // B pre-swizzled 32KB chunks
__device__ __align__(16) float g_part[(size_t)BATCH * D_MODEL];   // split-K partials
__device__ int g_done;
__device__ int g_flag[256];   // per (tile, kh)
__device__ int g_cflag[128];  // per B-chunk ready flag

// ---------------- reset: counters only (replaces convW pre-kernel) -------------
__global__ void reset_kernel() {
    const int t = threadIdx.x;
    if (t == 0) g_done = 0;
    g_flag[t] = 0;
    if (t < 128) g_cflag[t] = 0;
}

// ================================ mega kernel ==================================
#define GEMM_BLOCKS 256
#define DP_BLOCKS 16
#define TP_BLOCKS 24
#define PREP_TOTAL (DP_BLOCKS + TP_BLOCKS)
#define SST 40960
#define BOFF 8192
#define MB0 81920
#define MB1 81928
#define SMEM_BYTES 81952

__device__ __forceinline__ void ldsm4(uint32_t* r, uint32_t a) {
    asm volatile("ldmatrix.sync.aligned.m8n8.x4.shared.b16 {%0,%1,%2,%3}, [%4];"
                 : "=r"(r[0]), "=r"(r[1]), "=r"(r[2]), "=r"(r[3]) : "r"(a));
}
__device__ __forceinline__ void mma_fp16(float* c, const uint32_t* a, const uint32_t* b) {
    asm volatile(
        "mma.sync.aligned.m16n8k16.row.col.f32.f16.f16.f32 "
        "{%0,%1,%2,%3}, {%4,%5,%6,%7}, {%8,%9}, {%0,%1,%2,%3};"
        : "+f"(c[0]), "+f"(c[1]), "+f"(c[2]), "+f"(c[3])
        : "r"(a[0]), "r"(a[1]), "r"(a[2]), "r"(a[3]), "r"(b[0]), "r"(b[1]));
}
__device__ __forceinline__ int ld_acq(const int* p) {
    int v;
    asm volatile("ld.acquire.gpu.s32 %0, [%1];" : "=r"(v) : "l"(p));
    return v;
}
__device__ __forceinline__ void mbar_init(uint32_t a, uint32_t cnt) {
    asm volatile("mbarrier.init.shared.b64 [%0], %1;" :: "r"(a), "r"(cnt) : "memory");
}
__device__ __forceinline__ void bulkB(uint32_t dst, const void* src, uint32_t mbar) {
    asm volatile("mbarrier.arrive.expect_tx.shared.b64 _, [%0], %1;"
                 :: "r"(mbar), "r"(32768u) : "memory");
    asm volatile("cp.async.bulk.shared::cluster.global.mbarrier::complete_tx::bytes "
                 "[%0], [%1], %2, [%3];"
                 :: "r"(dst), "l"(src), "r"(32768u), "r"(mbar) : "memory");
}
__device__ __forceinline__ void mbar_wait(uint32_t a, uint32_t parity) {
    asm volatile(
        "{\n\t.reg .pred P;\n\t"
        "LW_%=:\n\t"
        "mbarrier.try_wait.parity.acquire.cta.shared::cta.b64 P, [%0], %1, 0x989680;\n\t"
        "@P bra LD_%=;\n\t"
        "bra LW_%=;\n\t"
        "LD_%=:\n\t}"
        :: "r"(a), "r"(parity) : "memory");
}
__device__ __forceinline__ void add_half8(float* hb, uint4 v) {
    const __half2* q = (const __half2*)&v;
#pragma unroll
    for (int p = 0; p < 4; p++) {
        float2 f = __half22float2(q[p]);
        hb[2 * p] += f.x;
        hb[2 * p + 1] += f.y;
    }
}
__device__ __forceinline__ void wait_chunk(int c) {
    while (ld_acq(&g_cflag[c]) == 0) __nanosleep(32);
}

__device__ void gemm_body(char* smem, int mt, int kh, const float* __restrict__ ce,
                          const int* __restrict__ nid, const int* __restrict__ cdep,
                          const float* __restrict__ ln_g, const float* __restrict__ ln_b,
                          float* __restrict__ out) {
    uint32_t sb;
    asm("{ .reg .u64 t; cvta.to.shared.u64 t, %1; cvt.u32.u64 %0, t; }"
        : "=r"(sb) : "l"(smem));
    const int t = threadIdx.x;
    const int lane = t & 31, w = t >> 5;
    const int wm = w & 1, wn = w >> 1;     // 2 x 4 warps; warp tile 32 x 64
    const int m0 = mt * 64;
    const int c0 = kh * 64;

    // A ldsm addressing
    const int arow0 = wm * 32 + (lane & 7) + ((lane >> 3) & 1) * 8;
    const uint32_t axor = (uint32_t)((arow0 & 7) << 4);
    const uint32_t khA = (uint32_t)((lane >> 4) * 16);
    // B ldsm addressing
    const int brow0 = wn * 64 + (lane & 7) + ((lane >> 4) & 1) * 8;
    const uint32_t bxor = (uint32_t)((lane & 7) << 4);
    const uint32_t khB = (uint32_t)(((lane >> 3) & 1) * 16);
    uint32_t arowb[2], browb[4];
#pragma unroll
    for (int i = 0; i < 2; i++) arowb[i] = (uint32_t)(arow0 + i * 16) * 128;
#pragma unroll
    for (int jp = 0; jp < 4; jp++) browb[jp] = (uint32_t)(brow0 + jp * 16) * 128;

    // A LDG/STS mapping
    const int prow = t >> 2, pcg = t & 3;
    const uint32_t prx = (uint32_t)((prow & 7) << 4);

    float acc[2][8][4];
#pragma unroll
    for (int i = 0; i < 2; i++)
#pragma unroll
        for (int j = 0; j < 8; j++)
#pragma unroll
            for (int q = 0; q < 4; q++) acc[i][j][q] = 0.f;

    float4 av[4];

    auto loadA = [&](int s) {
        const int c = c0 + s;
        const int a = c >> 2, kin = (c & 3) * 64;
        const float* p = ce + ((size_t)a * BATCH + m0 + prow) * D_MODEL + kin + pcg * 16;
#pragma unroll
        for (int q = 0; q < 4; q++) av[q] = *(const float4*)(p + q * 4);
    };
    auto stsA = [&](int buf) {
        const uint32_t da = sb + buf * SST;
        const uint32_t rbase = (uint32_t)prow * 128;
        uint32_t hv[8];
#pragma unroll
        for (int q = 0; q < 4; q++) {
            __half2 h01 = __floats2half2_rn(av[q].x, av[q].y);
            __half2 h23 = __floats2half2_rn(av[q].z, av[q].w);
            hv[2 * q]     = *(uint32_t*)&h01;
            hv[2 * q + 1] = *(uint32_t*)&h23;
        }
#pragma unroll
        for (int q = 0; q < 2; q++) {
            uint32_t off = rbase + (((uint32_t)(pcg * 32 + q * 16)) ^ prx);
            asm volatile("st.shared.v4.b32 [%0], {%1,%2,%3,%4};"
                         :: "r"(da + off), "r"(hv[4 * q]), "r"(hv[4 * q + 1]),
                            "r"(hv[4 * q + 2]), "r"(hv[4 * q + 3]));
        }
    };
    auto compute = [&](int buf) {
        const uint32_t SA = sb + buf * SST;
        const uint32_t SB = sb + buf * SST + BOFF;
#pragma unroll
        for (int kk = 0; kk < 4; kk++) {
            uint32_t ah[2][4], bh[4][4];
            const uint32_t ka = ((uint32_t)(kk * 32) + khA) ^ axor;
            const uint32_t kb = ((uint32_t)(kk * 32) + khB) ^ bxor;
#pragma unroll
            for (int i = 0; i < 2; i++) ldsm4(ah[i], SA + arowb[i] + ka);
#pragma unroll
            for (int jp = 0; jp < 4; jp++) ldsm4(bh[jp], SB + browb[jp] + kb);
#pragma unroll
            for (int i = 0; i < 2; i++)
#pragma unroll
                for (int j = 0; j < 8; j++)
                    mma_fp16(acc[i][j], ah[i], &bh[j >> 1][(j & 1) * 2]);
        }
    };

    // -------- prologue --------
    if (t == 0) { mbar_init(sb + MB0, 1); mbar_init(sb + MB1, 1); }
    __syncthreads();
    if (t == 0) {
        wait_chunk(c0);
        bulkB(sb + BOFF,       (const char*)g_WTsw + (size_t)(c0 + 0) * 32768, sb + MB0);
        wait_chunk(c0 + 1);
        bulkB(sb + SST + BOFF, (const char*)g_WTsw + (size_t)(c0 + 1) * 32768, sb + MB1);
    }
    loadA(0); stsA(0);
    loadA(1); stsA(1);
    if (t == 0) mbar_wait(sb + MB0, 0);   // B(0) ready (leader-only)
    __syncthreads();

    // -------- main loop: compute s; leader waits B(s+1) before stage barrier ----
    for (int s = 0; s < 64; s++) {
        const int buf = s & 1;
        if (s + 2 < 64) loadA(s + 2);
        compute(buf);
        if (t == 0 && s + 1 < 64) {
            mbar_wait(sb + (buf ? MB0 : MB1), (uint32_t)(((s + 1) >> 1) & 1));
            if (s + 2 < 64) wait_chunk(c0 + s + 2);
        }
        __syncthreads();  // buf fully read by all; B(s+1) visible to all
        if (s + 2 < 64) {
            if (t == 0)
                bulkB(sb + buf * SST + BOFF,
                      (const char*)g_WTsw + (size_t)(c0 + s + 2) * 32768,
                      sb + (buf ? MB1 : MB0));
            stsA(buf);  // A(s+2); readers separated by next stage's barrier
        }
    }

    // ---------------- symmetric epilogue: each CTA owns 32 rows -----------------
    const int cb = lane * 8;
    const int rbase = m0 + kh * 32 + w * 4;
    float4 gg0 = *(const float4*)(ln_g + cb), gg1 = *(const float4*)(ln_g + cb + 4);
    float4 bb0 = *(const float4*)(ln_b + cb), bb1 = *(const float4*)(ln_b + cb + 4);
    int dvals[4], tks[4];
#pragma unroll
    for (int q = 0; q < 4; q++) {
        dvals[q] = cdep[(size_t)lane * BATCH + (rbase + q)];
        tks[q]   = nid[rbase + q];
    }

    float* sh = (float*)smem;  // [32][260]
    if (wm == kh) {
        const int rb = lane >> 2;
        const int cbase = wn * 64 + (lane & 3) * 2;
#pragma unroll
        for (int i = 0; i < 2; i++)
#pragma unroll
            for (int j = 0; j < 8; j++) {
                const int rr = i * 16 + rb;
                const int cc = cbase + j * 8;
                sh[rr * 260 + cc]           = acc[i][j][0];
                sh[rr * 260 + cc + 1]       = acc[i][j][1];
                sh[(rr + 8) * 260 + cc]     = acc[i][j][2];
                sh[(rr + 8) * 260 + cc + 1] = acc[i][j][3];
            }
    } else {
#pragma unroll
        for (int i = 0; i < 2; i++)
#pragma unroll
            for (int j = 0; j < 8; j++) {
                const int r = m0 + wm * 32 + i * 16 + (lane >> 2);
                const int c = wn * 64 + j * 8 + (lane & 3) * 2;
                *(float2*)(g_part + (size_t)r * D_MODEL + c) =
                    make_float2(acc[i][j][0], acc[i][j][1]);
                *(float2*)(g_part + (size_t)(r + 8) * D_MODEL + c) =
                    make_float2(acc[i][j][2], acc[i][j][3]);
            }
    }
    __syncthreads();
    __threadfence();
    if (t == 0) {
        atomicAdd(&g_flag[2 * mt + kh], 1);
        while (ld_acq(&g_done) < PREP_TOTAL) __nanosleep(64);
        while (ld_acq(&g_flag[2 * mt + (1 - kh)]) == 0) __nanosleep(64);
    }
    __syncthreads();

    const float gj[8] = {gg0.x, gg0.y, gg0.z, gg0.w, gg1.x, gg1.y, gg1.z, gg1.w};
    const float lj[8] = {bb0.x, bb0.y, bb0.z, bb0.w, bb1.x, bb1.y, bb1.z, bb1.w};

#pragma unroll
    for (int q = 0; q < 4; q++) {
        const int r = rbase + q;
        float hb[8];
        const float* sp = sh + (w * 4 + q) * 260 + cb;
#pragma unroll
        for (int x = 0; x < 8; x++) hb[x] = sp[x];
        {
            float4 p0 = *(const float4*)(g_part + (size_t)r * D_MODEL + cb);
            float4 p1 = *(const float4*)(g_part + (size_t)r * D_MODEL + cb + 4);
            hb[0] += p0.x; hb[1] += p0.y; hb[2] += p0.z; hb[3] += p0.w;
            hb[4] += p1.x; hb[5] += p1.y; hb[6] += p1.z; hb[7] += p1.w;
        }
        add_half8(hb, *(const uint4*)(g_TPh + tks[q] * D_MODEL + cb));
#pragma unroll
        for (int a = 0; a < ARITY; a++) {
            const int d = __shfl_sync(0xFFFFFFFFu, dvals[q], a);
            add_half8(hb, *(const uint4*)(g_DPh + ((a * NDEPTH + d) << 8) + cb));
        }
        float s = 0.f, ss = 0.f;
#pragma unroll
        for (int x = 0; x < 8; x++) {
            hb[x] = fmaxf(hb[x], 0.f);
            s += hb[x];
            ss = fmaf(hb[x], hb[x], ss);
        }
#pragma unroll
        for (int o = 16; o > 0; o >>= 1) {
            s  += __shfl_xor_sync(0xFFFFFFFFu, s, o);
            ss += __shfl_xor_sync(0xFFFFFFFFu, ss, o);
        }
        const float mu = s * (1.f / 256.f);
        const float rs = rsqrtf(ss * (1.f / 256.f) - mu * mu + LN_EPS);
        float4 o0, o1;
        o0.x = (hb[0] - mu) * rs * gj[0] + lj[0];
        o0.y = (hb[1] - mu) * rs * gj[1] + lj[1];
        o0.z = (hb[2] - mu) * rs * gj[2] + lj[2];
        o0.w = (hb[3] - mu) * rs * gj[3] + lj[3];
        o1.x = (hb[4] - mu) * rs * gj[4] + lj[4];
        o1.y = (hb[5] - mu) * rs * gj[5] + lj[5];
        o1.z = (hb[6] - mu) * rs * gj[6] + lj[6];
        o1.w = (hb[7] - mu) * rs * gj[7] + lj[7];
        *(float4*)(out + (size_t)r * D_MODEL + cb)     = o0;
        *(float4*)(out + (size_t)r * D_MODEL + cb + 4) = o1;
    }
}

// ---------------- chunk conversion (runs on prep blocks, urgency-ordered) ------
__device__ void conv_group(char* sbuf, int kc, const float* __restrict__ W) {
    float (*ws)[257] = (float (*)[257])sbuf;
    const int t = threadIdx.x;
#pragma unroll
    for (int r = 0; r < 16; r++) {
        int kg = kc + r;
        ws[r][t] = W[(size_t)(256 + (kg >> 8) * 768 + (kg & 255)) * D_MODEL + t];
    }
    __syncthreads();
    uint32_t hi[8];
#pragma unroll
    for (int p = 0; p < 8; p++) {
        __half2 h = __floats2half2_rn(ws[2 * p][t], ws[2 * p + 1][t]);
        hi[p] = *(uint32_t*)&h;
    }
    const int c  = kc >> 6;
    const int ko = (kc & 63) >> 3;
    char* base = (char*)g_WTsw + (size_t)c * 32768 + (size_t)t * 128;
    const uint32_t x = (uint32_t)((t & 7) << 4);
    *(uint4*)(base + (((uint32_t)(ko * 16)) ^ x))       = make_uint4(hi[0], hi[1], hi[2], hi[3]);
    *(uint4*)(base + (((uint32_t)((ko + 1) * 16)) ^ x)) = make_uint4(hi[4], hi[5], hi[6], hi[7]);
    __syncthreads();
}

__device__ void conv_chunks(int pb, char* sbuf, const float* __restrict__ W) {
    for (int i = 0;; i++) {
        const int o = pb + 40 * i;          // urgency order
        if (o >= 128) break;
        const int c = ((o & 1) << 6) + (o >> 1);
#pragma unroll
        for (int g = 0; g < 4; g++)
            conv_group(sbuf, c * 64 + g * 16, W);
        asm volatile("fence.proxy.async;" ::: "memory");
        __threadfence();
        if (threadIdx.x == 0) atomicAdd(&g_cflag[c], 1);
    }
}

// ---------------- prep bodies (256 threads; packed into 40 blocks) -------------
__device__ void dp_body(int blk, char* sbuf,
                        const float* __restrict__ depth_emb,
                        const float* __restrict__ idx_emb,
                        const float* __restrict__ W) {
    float* de_s = (float*)sbuf;
    float* ie_s = de_s + NDEPTH * D_MODEL;
    const int j = threadIdx.x;
    for (int i = j; i < NDEPTH * D_MODEL; i += 256) de_s[i] = depth_emb[i];
    __syncthreads();
#pragma unroll
    for (int half = 0; half < 2; half++) {
        const int a = blk * 2 + half;
        ie_s[j] = idx_emb[a * D_MODEL + j];
        __syncthreads();
        float acc[NDEPTH];
#pragma unroll
        for (int m = 0; m < NDEPTH; m++) acc[m] = 0.f;
        float acci = 0.f;
        const float* Wde = W + (size_t)(512 + a * 768) * D_MODEL + j;
        const float* Wie = W + (size_t)(768 + a * 768) * D_MODEL + j;
#pragma unroll 8
        for (int k = 0; k < D_MODEL; k++) {
            float wde = Wde[k * D_MODEL];
            float wie = Wie[k * D_MODEL];
            acci = fmaf(ie_s[k], wie, acci);
#pragma unroll
            for (int m = 0; m < NDEPTH; m++)
                acc[m] = fmaf(de_s[m * D_MODEL + k], wde, acc[m]);
        }
#pragma unroll
        for (int m = 0; m < NDEPTH; m++)
            g_DPh[(a * NDEPTH + m) * D_MODEL + j] = __float2half_rn(acc[m] + acci);
        __syncthreads();
    }
    __threadfence();
    if (threadIdx.x == 0) atomicAdd(&g_done, 1);
}

__device__ void tp_body(int blk, char* sbuf,
                        const float* __restrict__ token_emb,
                        const float* __restrict__ W,
                        const float* __restrict__ bvec) {
    float* te_s = (float*)sbuf;
    const int j = threadIdx.x;
    const float bj = bvec[j];
    const float* Wt = W + j;
    for (int c = 0; c < 6; c++) {
        const int v0 = blk * 48 + c * 8;
        if (v0 >= VOCAB) break;
#pragma unroll
        for (int m = 0; m < 8; m++) {
            int v = v0 + m;
            te_s[m * D_MODEL + j] = (v < VOCAB) ? token_emb[v * D_MODEL + j] : 0.f;
        }
        __syncthreads();
        float acc[8];
#pragma unroll
        for (int m = 0; m < 8; m++) acc[m] = bj;
#pragma unroll 8
        for (int k = 0; k < D_MODEL; k++) {
            float wv = Wt[k * D_MODEL];
#pragma unroll
            for (int m = 0; m < 8; m++)
                acc[m] = fmaf(te_s[m * D_MODEL + k], wv, acc[m]);
        }
#pragma unroll
        for (int m = 0; m < 8; m++) {
            int v = v0 + m;
            if (v < VOCAB) g_TPh[v * D_MODEL + j] = __float2half_rn(acc[m]);
        }
        __syncthreads();
    }
    __threadfence();
    if (threadIdx.x == 0) atomicAdd(&g_done, 1);
}

__global__ __launch_bounds__(256, 2)
void mega_kernel(const float* __restrict__ ce,
                 const float* __restrict__ depth_emb,
                 const float* __restrict__ idx_emb,
                 const float* __restrict__ token_emb,
                 const float* __restrict__ W,
                 const float* __restrict__ bvec,
                 const int* __restrict__ nid,
                 const int* __restrict__ cdep,
                 const float* __restrict__ ln_g,
                 const float* __restrict__ ln_b,
                 float* __restrict__ out) {
    extern __shared__ char smem[];
    const int b = blockIdx.x;
    if (b < GEMM_BLOCKS) {
        gemm_body(smem, b >> 1, b & 1, ce, nid, cdep, ln_g, ln_b, out);
    } else {
        const int pb = b - GEMM_BLOCKS;       // 0..39
        conv_chunks(pb, smem, W);             // B chunks first (GEMM is waiting)
        __syncthreads();
        if (pb < DP_BLOCKS) dp_body(pb, smem, depth_emb, idx_emb, W);
        else                tp_body(pb - DP_BLOCKS, smem, token_emb, W, bvec);
    }
}

// --------------------------------- launch -------------------------------------
extern "C" void kernel_launch(void* const* d_in, const int* in_sizes, int n_in,
                              void* d_out, int out_size) {
    const int*   nid          = (const int*)d_in[0];
    const float* child_embs   = (const float*)d_in[1];
    const int*   child_depths = (const int*)d_in[2];
    const float* token_emb    = (const float*)d_in[3];
    const float* depth_emb    = (const float*)d_in[4];
    const float* idx_emb      = (const float*)d_in[5];
    const float* W            = (const float*)d_in[6];
    const float* bvec         = (const float*)d_in[7];
    const float* ln_g         = (const float*)d_in[8];
    const float* ln_b         = (const float*)d_in[9];
    float* out = (float*)d_out;

    cudaFuncSetAttribute(mega_kernel, cudaFuncAttributeMaxDynamicSharedMemorySize, SMEM_BYTES);

    reset_kernel<<<1, 256>>>();
    mega_kernel<<<GEMM_BLOCKS + PREP_TOTAL, 256, SMEM_BYTES>>>(
        child_embs, depth_emb, idx_emb, token_emb, W, bvec,
        nid, child_depths, ln_g, ln_b, out);
}